// round 11
// baseline (speedup 1.0000x reference)
#include <cuda_runtime.h>
#include <cuda_fp16.h>
#include <cstdint>
#include <cstddef>

#define N_SENT 32768
#define EMSIZE 2048
#define NCLASS 128
#define NCOLS  384   // 3 taps * 128
#define TAPS   3

// ---------------- scratch (allocation-free) ----------------
__device__ __half g_Hh[(size_t)N_SENT * NCLASS];           // tanh hidden, fp16
__device__ __half g_Gh[(size_t)N_SENT * NCOLS];            // stage-2 GEMM out, fp16
__device__ __half g_W1h[(size_t)TAPS * NCLASS * EMSIZE];   // [tap][c][e] K-major fp16
__device__ __half g_W2h[(size_t)TAPS * NCLASS * NCLASS];   // [tap][c][k] K-major fp16
__device__ float  g_h1[NCLASS];                            // tanh(x[1]@W1[0]+b1) for row-1 fallback

// ---------------- PTX helpers ----------------
__device__ __forceinline__ uint32_t smem_u32(const void* p) {
    uint32_t a;
    asm("{ .reg .u64 t; cvta.to.shared.u64 t, %1; cvt.u32.u64 %0, t; }" : "=r"(a) : "l"(p));
    return a;
}
__device__ __forceinline__ void cp_async16(uint32_t saddr, const void* g) {
    asm volatile("cp.async.ca.shared.global [%0], [%1], 16;" :: "r"(saddr), "l"(g));
}
__device__ __forceinline__ void cp_commit() {
    asm volatile("cp.async.commit_group;" ::: "memory");
}
template<int n> __device__ __forceinline__ void cp_wait() {
    asm volatile("cp.async.wait_group %0;" :: "n"(n) : "memory");
}
__device__ __forceinline__ void ldsm4(uint32_t r[4], uint32_t saddr) {
    asm volatile("ldmatrix.sync.aligned.m8n8.x4.shared.b16 {%0,%1,%2,%3}, [%4];"
                 : "=r"(r[0]), "=r"(r[1]), "=r"(r[2]), "=r"(r[3]) : "r"(saddr));
}
__device__ __forceinline__ void mma16816(float d[4], const uint32_t a[4], const uint32_t b[2]) {
    asm volatile(
        "mma.sync.aligned.m16n8k16.row.col.f32.f16.f16.f32 "
        "{%0,%1,%2,%3},{%4,%5,%6,%7},{%8,%9},{%0,%1,%2,%3};"
        : "+f"(d[0]), "+f"(d[1]), "+f"(d[2]), "+f"(d[3])
        : "r"(a[0]), "r"(a[1]), "r"(a[2]), "r"(a[3]), "r"(b[0]), "r"(b[1]));
}

// Swizzled 16B-chunk offset inside a 128-row x 32-half (64B/row) tile.
__device__ __forceinline__ uint32_t tile_off(int row, int c) {
    return (uint32_t)(row * 64 + ((c ^ ((row >> 1) & 3)) << 4));
}

#define STAGE_BYTES 16384     // A tile 8KB + B tile 8KB
#define NSTAGES     4
#define SMEM_BYTES  (STAGE_BYTES * NSTAGES)   // 64 KB dynamic

// chunk q (K=32 slice of the fused K=6144 loop) -> (tap, k2): tap cycles fastest
__device__ __forceinline__ void chunk_decode(int q, int& tp, int& k2) {
    k2 = q / 3; tp = q - 3 * k2;
}

// ============================================================================
// K1 fused: H[p] = tanh( Σ_k x[p-k]@W1[k] + cnt(p)*b1 ),  one CTA = 128 rows.
// K=6144 GEMM, chunk kt -> tap kt%3 (A rows shifted by tap; same A slab re-read
// 2 chunks later -> L1/L2 hit, DRAM reads x once). 4-stage ring identical to R10.
// ============================================================================
#define KT1 (TAPS * EMSIZE / 32)   // 192

__global__ void __launch_bounds__(256, 2)
gemm1_fused(const float* __restrict__ x,
            const __half* __restrict__ W1h,
            const float* __restrict__ b1,
            __half* __restrict__ H)
{
    extern __shared__ __align__(128) uint8_t dsm[];

    const int tid  = threadIdx.x;
    const int lane = tid & 31;
    const int warp = tid >> 5;
    const int wm   = warp >> 1;   // 0..3
    const int wn   = warp & 1;    // 0..1
    const int m0   = blockIdx.x * 128;

    const int lrow = tid >> 2;       // 0..63 (second chunk at +64)
    const int lc   = tid & 3;
    const uint32_t soff1 = tile_off(lrow, lc);
    const uint32_t soff2 = soff1 + 64 * 64;

    const uint32_t sbase = smem_u32(dsm);
    uint32_t aoff[2][2], boff[4][2];
    {
        const int arow0 = wm * 32 + (lane & 7) + 8 * ((lane >> 3) & 1);
        const int acadd = lane >> 4;
        const int brow0 = wn * 64 + (lane & 7) + 8 * (lane >> 4);
        const int bcadd = (lane >> 3) & 1;
        #pragma unroll
        for (int kk = 0; kk < 2; kk++) {
            #pragma unroll
            for (int mi = 0; mi < 2; mi++)
                aoff[mi][kk] = tile_off(arow0 + mi * 16, kk * 2 + acadd);
            #pragma unroll
            for (int nip = 0; nip < 4; nip++)
                boff[nip][kk] = tile_off(brow0 + nip * 16, kk * 2 + bcadd);
        }
    }

    float acc[2][8][4];
    #pragma unroll
    for (int mi = 0; mi < 2; mi++)
        #pragma unroll
        for (int ni = 0; ni < 8; ni++)
            #pragma unroll
            for (int q = 0; q < 4; q++) acc[mi][ni][q] = 0.f;

    __half2 st[8];   // converted A chunk kt (held in regs at iter kt)

    // A chunk loader: rows (m0+lrow-tp) and (m0+lrow+64-tp); first may be <0 (zero-fill).
    auto loadA = [&](int tp, int k2) {
        const int ar = m0 + lrow - tp;
        const float* p2 = x + (size_t)(ar + 64) * EMSIZE + k2 * 32 + lc * 8;
        if (ar >= 0) {
            const float* p1 = x + (size_t)ar * EMSIZE + k2 * 32 + lc * 8;
            float4 v0 = *(const float4*)p1, v1 = *(const float4*)(p1 + 4);
            st[0] = __floats2half2_rn(v0.x, v0.y); st[1] = __floats2half2_rn(v0.z, v0.w);
            st[2] = __floats2half2_rn(v1.x, v1.y); st[3] = __floats2half2_rn(v1.z, v1.w);
        } else {
            st[0] = st[1] = st[2] = st[3] = __half2half2(__float2half(0.f));
        }
        float4 w0 = *(const float4*)p2, w1 = *(const float4*)(p2 + 4);
        st[4] = __floats2half2_rn(w0.x, w0.y); st[5] = __floats2half2_rn(w0.z, w0.w);
        st[6] = __floats2half2_rn(w1.x, w1.y); st[7] = __floats2half2_rn(w1.z, w1.w);
    };

    // ---- prologue: B chunks 0,1 (taps 0,1, k2=0); A chunk 0 -> regs ----
    #pragma unroll
    for (int s = 0; s < 2; s++) {
        const uint32_t sp = sbase + s * STAGE_BYTES;
        const __half* Bb = W1h + (size_t)s * NCLASS * EMSIZE;   // tap=s, k2=0
        cp_async16(sp + 8192 + soff1, Bb + (size_t)lrow * EMSIZE + lc * 8);
        cp_async16(sp + 8192 + soff2, Bb + (size_t)(lrow + 64) * EMSIZE + lc * 8);
        cp_commit();
    }
    loadA(0, 0);

    for (int kt = 0; kt < KT1; kt++) {
        const uint32_t sbuf = sbase + (uint32_t)(kt & 3) * STAGE_BYTES;

        // STS converted A chunk kt -> stage kt%4 (last read at kt-4: safe)
        *(uint4*)(dsm + (kt & 3) * STAGE_BYTES + soff1) = *(uint4*)(&st[0]);
        *(uint4*)(dsm + (kt & 3) * STAGE_BYTES + soff2) = *(uint4*)(&st[4]);

        // prefetch B chunk kt+2 -> stage (kt+2)%4 (!= (kt-1)%4: safe pre-barrier)
        if (kt + 2 < KT1) {
            int tp, k2; chunk_decode(kt + 2, tp, k2);
            const uint32_t sp = sbase + (uint32_t)((kt + 2) & 3) * STAGE_BYTES;
            const __half* Bb = W1h + (size_t)tp * NCLASS * EMSIZE + k2 * 32;
            cp_async16(sp + 8192 + soff1, Bb + (size_t)lrow * EMSIZE + lc * 8);
            cp_async16(sp + 8192 + soff2, Bb + (size_t)(lrow + 64) * EMSIZE + lc * 8);
            cp_commit();
        }

        // LDG + convert A chunk kt+1 (overlaps compute)
        if (kt + 1 < KT1) {
            int tp, k2; chunk_decode(kt + 1, tp, k2);
            loadA(tp, k2);
        }

        if      (kt + 2 < KT1) cp_wait<2>();
        else if (kt + 1 < KT1) cp_wait<1>();
        else                   cp_wait<0>();
        __syncthreads();   // single barrier per iteration

        #pragma unroll
        for (int kk = 0; kk < 2; kk++) {
            uint32_t a[2][4], b[4][4];
            #pragma unroll
            for (int mi = 0; mi < 2; mi++) ldsm4(a[mi], sbuf + aoff[mi][kk]);
            #pragma unroll
            for (int nip = 0; nip < 4; nip++) ldsm4(b[nip], sbuf + 8192 + boff[nip][kk]);
            #pragma unroll
            for (int mi = 0; mi < 2; mi++)
                #pragma unroll
                for (int ni = 0; ni < 8; ni++)
                    mma16816(acc[mi][ni], a[mi], &b[ni >> 1][(ni & 1) * 2]);
        }
    }

    // epilogue: H = tanh(S + cnt*b1), fp16
    const int gid = lane >> 2, tig = lane & 3;
    #pragma unroll
    for (int mi = 0; mi < 2; mi++) {
        const int r0 = m0 + wm * 32 + mi * 16 + gid;
        const float c0 = fminf((float)r0, 2.f) + 1.f;
        const float c1 = fminf((float)(r0 + 8), 2.f) + 1.f;
        #pragma unroll
        for (int ni = 0; ni < 8; ni++) {
            const int col = wn * 64 + ni * 8 + tig * 2;
            const float ba = b1[col], bb = b1[col + 1];
            __half2 lo = __floats2half2_rn(tanhf(acc[mi][ni][0] + c0 * ba),
                                           tanhf(acc[mi][ni][1] + c0 * bb));
            __half2 hi = __floats2half2_rn(tanhf(acc[mi][ni][2] + c1 * ba),
                                           tanhf(acc[mi][ni][3] + c1 * bb));
            *(__half2*)&H[(size_t)r0 * NCLASS + col]       = lo;
            *(__half2*)&H[(size_t)(r0 + 8) * NCLASS + col] = hi;
        }
    }
}

// ============================================================================
// K3: G = H @ W2 per tap (fp16 in, fp16 out) — R10-proven structure, K=128.
// ============================================================================
__global__ void __launch_bounds__(256, 2)
gemm2_kernel(const __half* __restrict__ Ah,
             const __half* __restrict__ Bg,
             __half* __restrict__ C,
             int K)
{
    extern __shared__ __align__(128) uint8_t dsm[];

    const int tid  = threadIdx.x;
    const int lane = tid & 31;
    const int warp = tid >> 5;
    const int wm   = warp >> 1;
    const int wn   = warp & 1;
    const int tap  = blockIdx.x % TAPS;
    const int m0   = (blockIdx.x / TAPS) * 128;
    const __half* Bt = Bg + (size_t)tap * 128 * K;
    const int KT = K >> 5;

    const int lrow = tid >> 2;
    const int lc   = tid & 3;
    const uint32_t soff1 = tile_off(lrow, lc);
    const uint32_t soff2 = soff1 + 64 * 64;

    const uint32_t sbase = smem_u32(dsm);
    uint32_t aoff[2][2], boff[4][2];
    {
        const int arow0 = wm * 32 + (lane & 7) + 8 * ((lane >> 3) & 1);
        const int acadd = lane >> 4;
        const int brow0 = wn * 64 + (lane & 7) + 8 * (lane >> 4);
        const int bcadd = (lane >> 3) & 1;
        #pragma unroll
        for (int kk = 0; kk < 2; kk++) {
            #pragma unroll
            for (int mi = 0; mi < 2; mi++)
                aoff[mi][kk] = tile_off(arow0 + mi * 16, kk * 2 + acadd);
            #pragma unroll
            for (int nip = 0; nip < 4; nip++)
                boff[nip][kk] = tile_off(brow0 + nip * 16, kk * 2 + bcadd);
        }
    }

    float acc[2][8][4];
    #pragma unroll
    for (int mi = 0; mi < 2; mi++)
        #pragma unroll
        for (int ni = 0; ni < 8; ni++)
            #pragma unroll
            for (int q = 0; q < 4; q++) acc[mi][ni][q] = 0.f;

    #pragma unroll
    for (int s = 0; s < 2; s++) {
        const uint32_t sp = sbase + s * STAGE_BYTES;
        const int kb = s << 5;
        cp_async16(sp + soff1, Ah + (size_t)(m0 + lrow) * K + kb + lc * 8);
        cp_async16(sp + soff2, Ah + (size_t)(m0 + lrow + 64) * K + kb + lc * 8);
        cp_async16(sp + 8192 + soff1, Bt + (size_t)lrow * K + kb + lc * 8);
        cp_async16(sp + 8192 + soff2, Bt + (size_t)(lrow + 64) * K + kb + lc * 8);
        cp_commit();
    }

    for (int kt = 0; kt < KT; kt++) {
        const uint32_t sbuf = sbase + (uint32_t)(kt & 3) * STAGE_BYTES;

        if (kt + 2 < KT) {
            const int kb = (kt + 2) << 5;
            const uint32_t sp = sbase + (uint32_t)((kt + 2) & 3) * STAGE_BYTES;
            cp_async16(sp + soff1, Ah + (size_t)(m0 + lrow) * K + kb + lc * 8);
            cp_async16(sp + soff2, Ah + (size_t)(m0 + lrow + 64) * K + kb + lc * 8);
            cp_async16(sp + 8192 + soff1, Bt + (size_t)lrow * K + kb + lc * 8);
            cp_async16(sp + 8192 + soff2, Bt + (size_t)(lrow + 64) * K + kb + lc * 8);
            cp_commit();
        }

        if      (kt + 2 < KT) cp_wait<2>();
        else if (kt + 1 < KT) cp_wait<1>();
        else                  cp_wait<0>();
        __syncthreads();

        #pragma unroll
        for (int kk = 0; kk < 2; kk++) {
            uint32_t a[2][4], b[4][4];
            #pragma unroll
            for (int mi = 0; mi < 2; mi++) ldsm4(a[mi], sbuf + aoff[mi][kk]);
            #pragma unroll
            for (int nip = 0; nip < 4; nip++) ldsm4(b[nip], sbuf + 8192 + boff[nip][kk]);
            #pragma unroll
            for (int mi = 0; mi < 2; mi++)
                #pragma unroll
                for (int ni = 0; ni < 8; ni++)
                    mma16816(acc[mi][ni], a[mi], &b[ni >> 1][(ni & 1) * 2]);
        }
    }

    const int gid = lane >> 2, tig = lane & 3;
    #pragma unroll
    for (int mi = 0; mi < 2; mi++) {
        const int r0 = m0 + wm * 32 + mi * 16 + gid;
        #pragma unroll
        for (int ni = 0; ni < 8; ni++) {
            const int col = tap * 128 + wn * 64 + ni * 8 + tig * 2;
            __half2 lo = __floats2half2_rn(acc[mi][ni][0], acc[mi][ni][1]);
            __half2 hi = __floats2half2_rn(acc[mi][ni][2], acc[mi][ni][3]);
            *(__half2*)&C[(size_t)r0 * NCOLS + col]       = lo;
            *(__half2*)&C[(size_t)(r0 + 8) * NCOLS + col] = hi;
        }
    }
}

// ---------------- weight transpose + fp16 convert ----------------
__global__ void transpose_w_h_kernel(const float* __restrict__ W, __half* __restrict__ Wt,
                                     int E, int C)
{
    __shared__ float tile[32][33];
    const int t  = blockIdx.z;
    const int e0 = blockIdx.x << 5, c0 = blockIdx.y << 5;
    const float* src = W + (size_t)t * E * C;
    __half* dst = Wt + (size_t)t * C * E;
    #pragma unroll
    for (int j = 0; j < 32; j += 8)
        tile[threadIdx.y + j][threadIdx.x] =
            src[(size_t)(e0 + threadIdx.y + j) * C + c0 + threadIdx.x];
    __syncthreads();
    #pragma unroll
    for (int j = 0; j < 32; j += 8)
        dst[(size_t)(c0 + threadIdx.y + j) * E + e0 + threadIdx.x] =
            __float2half_rn(tile[threadIdx.x][threadIdx.y + j]);
}

// ---------------- row-1 fallback hidden: h1 = tanh(x[1] @ W1[0] + b1) ----------------
__global__ void row1_kernel(const float* __restrict__ x, const float* __restrict__ W1,
                            const float* __restrict__ b1, float* __restrict__ h1)
{
    __shared__ float red[256];
    const int tid = threadIdx.x;          // 256 threads
    const int c = tid & 127, half_ = tid >> 7;
    const float* xr = x + EMSIZE;         // row 1
    float acc = 0.f;
    const int e0 = half_ * 1024;
    #pragma unroll 8
    for (int e = 0; e < 1024; e++)
        acc += xr[e0 + e] * W1[(size_t)(e0 + e) * NCLASS + c];
    red[tid] = acc;
    __syncthreads();
    if (half_ == 0)
        h1[c] = tanhf(red[c] + red[c + 128] + b1[c]);
}

// ---------------- K4: stage-2 combine + fallback + log_softmax (warp/row) ----------------
__global__ void stage2_softmax_kernel(const __half* __restrict__ G,
                                      const float4* __restrict__ W2_4,
                                      const float4* __restrict__ h1_4,
                                      const float4* __restrict__ b2_4,
                                      float4* __restrict__ out4)
{
    const int warp = threadIdx.x >> 5, lane = threadIdx.x & 31;
    const int i = blockIdx.x * 8 + warp;
    float4 z;
    float4 bb = b2_4[lane];
    if (i >= 2) {
        const __half2* g0 = (const __half2*)&G[(size_t)(i - 2) * NCOLS + 4 * lane];
        const __half2* g1 = (const __half2*)&G[(size_t)(i - 1) * NCOLS + 128 + 4 * lane];
        const __half2* g2 = (const __half2*)&G[(size_t)i * NCOLS + 256 + 4 * lane];
        float2 a0 = __half22float2(g0[0]), a1 = __half22float2(g0[1]);
        float2 b0 = __half22float2(g1[0]), b1v = __half22float2(g1[1]);
        float2 c0 = __half22float2(g2[0]), c1 = __half22float2(g2[1]);
        z.x = a0.x + b0.x + c0.x + 3.f * bb.x;
        z.y = a0.y + b0.y + c0.y + 3.f * bb.y;
        z.z = a1.x + b1v.x + c1.x + 3.f * bb.z;
        z.w = a1.y + b1v.y + c1.y + 3.f * bb.w;
    } else if (i == 0) {
        // H0[0] == H[0] (cnt=1), so Z0 = G[0, block0] + b2
        const __half2* g0 = (const __half2*)&G[4 * lane];
        float2 a0 = __half22float2(g0[0]), a1 = __half22float2(g0[1]);
        z.x = a0.x + bb.x; z.y = a0.y + bb.y;
        z.z = a1.x + bb.z; z.w = a1.y + bb.w;
    } else {
        // i == 1: h1 precomputed (tanh applied)
        float4 h = h1_4[lane];
        float4 acc = bb;
        for (int j = 0; j < 32; j++) {
            float hx = __shfl_sync(0xffffffffu, h.x, j);
            float hy = __shfl_sync(0xffffffffu, h.y, j);
            float hz = __shfl_sync(0xffffffffu, h.z, j);
            float hw = __shfl_sync(0xffffffffu, h.w, j);
            int k = 4 * j;
            float4 w0 = W2_4[(size_t)(k + 0) * 32 + lane];
            float4 w1 = W2_4[(size_t)(k + 1) * 32 + lane];
            float4 w2 = W2_4[(size_t)(k + 2) * 32 + lane];
            float4 w3 = W2_4[(size_t)(k + 3) * 32 + lane];
            acc.x += hx * w0.x + hy * w1.x + hz * w2.x + hw * w3.x;
            acc.y += hx * w0.y + hy * w1.y + hz * w2.y + hw * w3.y;
            acc.z += hx * w0.z + hy * w1.z + hz * w2.z + hw * w3.z;
            acc.w += hx * w0.w + hy * w1.w + hz * w2.w + hw * w3.w;
        }
        z = acc;
    }
    float m = fmaxf(fmaxf(z.x, z.y), fmaxf(z.z, z.w));
    #pragma unroll
    for (int o = 16; o > 0; o >>= 1) m = fmaxf(m, __shfl_xor_sync(0xffffffffu, m, o));
    float s = __expf(z.x - m) + __expf(z.y - m) + __expf(z.z - m) + __expf(z.w - m);
    #pragma unroll
    for (int o = 16; o > 0; o >>= 1) s += __shfl_xor_sync(0xffffffffu, s, o);
    float ls = m + __logf(s);
    out4[(size_t)i * 32 + lane] = make_float4(z.x - ls, z.y - ls, z.z - ls, z.w - ls);
}

// ---------------- launch ----------------
extern "C" void kernel_launch(void* const* d_in, const int* in_sizes, int n_in,
                              void* d_out, int out_size)
{
    const float* x  = (const float*)d_in[0];
    const float* W1 = (const float*)d_in[1];
    const float* b1 = (const float*)d_in[2];
    const float* W2 = (const float*)d_in[3];
    const float* b2 = (const float*)d_in[4];
    float* out = (float*)d_out;

    __half *Hh, *Gh, *W1h, *W2h; float* h1;
    cudaGetSymbolAddress((void**)&Hh,  g_Hh);
    cudaGetSymbolAddress((void**)&Gh,  g_Gh);
    cudaGetSymbolAddress((void**)&W1h, g_W1h);
    cudaGetSymbolAddress((void**)&W2h, g_W2h);
    cudaGetSymbolAddress((void**)&h1,  g_h1);

    static bool attr_done = false;
    if (!attr_done) {
        cudaFuncSetAttribute((const void*)gemm1_fused,
                             cudaFuncAttributeMaxDynamicSharedMemorySize, SMEM_BYTES);
        cudaFuncSetAttribute((const void*)gemm2_kernel,
                             cudaFuncAttributeMaxDynamicSharedMemorySize, SMEM_BYTES);
        attr_done = true;
    }

    // 0,1: transpose + fp16-convert weights (K-major)
    transpose_w_h_kernel<<<dim3(EMSIZE / 32, NCLASS / 32, TAPS), dim3(32, 8)>>>(W1, W1h, EMSIZE, NCLASS);
    transpose_w_h_kernel<<<dim3(NCLASS / 32, NCLASS / 32, TAPS), dim3(32, 8)>>>(W2, W2h, NCLASS, NCLASS);

    // 2: row-1 fallback hidden vector
    row1_kernel<<<1, 256>>>(x, W1, b1, h1);

    // 3: fused stage-1 (K=6144 tap-interleaved GEMM + tanh epilogue -> H fp16)
    gemm1_fused<<<N_SENT / 128, 256, SMEM_BYTES>>>(x, W1h, b1, Hh);

    // 4: G = H @ W2 (fp16 out)
    gemm2_kernel<<<(N_SENT / 128) * TAPS, 256, SMEM_BYTES>>>(Hh, W2h, Gh, NCLASS);

    // 5: Z combine + fallback + log_softmax
    stage2_softmax_kernel<<<N_SENT / 8, 256>>>(
        Gh, (const float4*)W2, (const float4*)h1, (const float4*)b2, (float4*)out);
}

// round 12
// speedup vs baseline: 1.0942x; 1.0942x over previous
#include <cuda_runtime.h>
#include <cuda_fp16.h>
#include <cstdint>
#include <cstddef>

#define N_SENT 32768
#define EMSIZE 2048
#define NCLASS 128
#define NCOLS  384   // 3 taps * 128
#define TAPS   3

// ---------------- scratch (allocation-free) ----------------
__device__ __half g_Yh[(size_t)N_SENT * NCOLS];            // stage-1 per-tap GEMM out, fp16
__device__ __half g_Gh[(size_t)N_SENT * NCOLS];            // stage-2 GEMM out, fp16
__device__ __half g_Hh[(size_t)N_SENT * NCLASS];           // tanh hidden, fp16
__device__ __half g_W1h[(size_t)TAPS * NCLASS * EMSIZE];   // [tap][c][e] K-major fp16
__device__ __half g_W2h[(size_t)TAPS * NCLASS * NCLASS];   // [tap][c][k] K-major fp16

// ---------------- PTX helpers ----------------
__device__ __forceinline__ uint32_t smem_u32(const void* p) {
    uint32_t a;
    asm("{ .reg .u64 t; cvta.to.shared.u64 t, %1; cvt.u32.u64 %0, t; }" : "=r"(a) : "l"(p));
    return a;
}
__device__ __forceinline__ void cp_async16(uint32_t saddr, const void* g) {
    asm volatile("cp.async.ca.shared.global [%0], [%1], 16;" :: "r"(saddr), "l"(g));
}
__device__ __forceinline__ void cp_commit() {
    asm volatile("cp.async.commit_group;" ::: "memory");
}
template<int n> __device__ __forceinline__ void cp_wait() {
    asm volatile("cp.async.wait_group %0;" :: "n"(n) : "memory");
}
__device__ __forceinline__ void ldsm4(uint32_t r[4], uint32_t saddr) {
    asm volatile("ldmatrix.sync.aligned.m8n8.x4.shared.b16 {%0,%1,%2,%3}, [%4];"
                 : "=r"(r[0]), "=r"(r[1]), "=r"(r[2]), "=r"(r[3]) : "r"(saddr));
}
__device__ __forceinline__ void mma16816(float d[4], const uint32_t a[4], const uint32_t b[2]) {
    asm volatile(
        "mma.sync.aligned.m16n8k16.row.col.f32.f16.f16.f32 "
        "{%0,%1,%2,%3},{%4,%5,%6,%7},{%8,%9},{%0,%1,%2,%3};"
        : "+f"(d[0]), "+f"(d[1]), "+f"(d[2]), "+f"(d[3])
        : "r"(a[0]), "r"(a[1]), "r"(a[2]), "r"(a[3]), "r"(b[0]), "r"(b[1]));
}

// Swizzled 16B-chunk offset inside a 128-row x 32-half (64B/row) tile.
__device__ __forceinline__ uint32_t tile_off(int row, int c) {
    return (uint32_t)(row * 64 + ((c ^ ((row >> 1) & 3)) << 4));
}

#define STAGE_BYTES 16384     // A tile 8KB + B tile 8KB
#define NSTAGES     4
#define SMEM_BYTES  (STAGE_BYTES * NSTAGES)   // 64 KB dynamic

// ---------------- K1: fp16 tensor-core GEMM (R10-proven: 4 stages, K-chunk 32) ----------------
// Grid 1-D: bid -> (m_tile = bid/3, tap = bid%3); consecutive taps share A via L2.
// A fp32 converted in-kernel; C written fp16 at NCOLS stride (col offset tap*128).
__global__ void __launch_bounds__(256, 2)
gemm1_kernel(const float* __restrict__ Af,
             const __half* __restrict__ Bg,
             __half* __restrict__ C,
             int K)
{
    extern __shared__ __align__(128) uint8_t dsm[];

    const int tid  = threadIdx.x;
    const int lane = tid & 31;
    const int warp = tid >> 5;
    const int wm   = warp >> 1;   // 0..3
    const int wn   = warp & 1;    // 0..1
    const int tap  = blockIdx.x % TAPS;
    const int m0   = (blockIdx.x / TAPS) * 128;
    const __half* Bt = Bg + (size_t)tap * 128 * K;
    const int KT = K >> 5;

    const int lrow = tid >> 2;       // 0..63 (second chunk at +64)
    const int lc   = tid & 3;
    const uint32_t soff1 = tile_off(lrow, lc);
    const uint32_t soff2 = soff1 + 64 * 64;

    const uint32_t sbase = smem_u32(dsm);
    uint32_t aoff[2][2], boff[4][2];
    {
        const int arow0 = wm * 32 + (lane & 7) + 8 * ((lane >> 3) & 1);
        const int acadd = lane >> 4;
        const int brow0 = wn * 64 + (lane & 7) + 8 * (lane >> 4);
        const int bcadd = (lane >> 3) & 1;
        #pragma unroll
        for (int kk = 0; kk < 2; kk++) {
            #pragma unroll
            for (int mi = 0; mi < 2; mi++)
                aoff[mi][kk] = tile_off(arow0 + mi * 16, kk * 2 + acadd);
            #pragma unroll
            for (int nip = 0; nip < 4; nip++)
                boff[nip][kk] = tile_off(brow0 + nip * 16, kk * 2 + bcadd);
        }
    }

    float acc[2][8][4];
    #pragma unroll
    for (int mi = 0; mi < 2; mi++)
        #pragma unroll
        for (int ni = 0; ni < 8; ni++)
            #pragma unroll
            for (int q = 0; q < 4; q++) acc[mi][ni][q] = 0.f;

    __half2 st[8];   // converted A chunk kt (held in regs at iter kt)

    // ---- prologue: B chunks 0,1 via cp.async; A chunk 0 -> regs ----
    #pragma unroll
    for (int s = 0; s < 2; s++) {
        const uint32_t sp = sbase + s * STAGE_BYTES;
        const int kb = s << 5;
        cp_async16(sp + 8192 + soff1, Bt + (size_t)lrow * K + kb + lc * 8);
        cp_async16(sp + 8192 + soff2, Bt + (size_t)(lrow + 64) * K + kb + lc * 8);
        cp_commit();
    }
    {
        const float* p1 = Af + (size_t)(m0 + lrow) * K + lc * 8;
        const float* p2 = Af + (size_t)(m0 + lrow + 64) * K + lc * 8;
        float4 v0 = *(const float4*)p1, v1 = *(const float4*)(p1 + 4);
        float4 w0 = *(const float4*)p2, w1 = *(const float4*)(p2 + 4);
        st[0] = __floats2half2_rn(v0.x, v0.y); st[1] = __floats2half2_rn(v0.z, v0.w);
        st[2] = __floats2half2_rn(v1.x, v1.y); st[3] = __floats2half2_rn(v1.z, v1.w);
        st[4] = __floats2half2_rn(w0.x, w0.y); st[5] = __floats2half2_rn(w0.z, w0.w);
        st[6] = __floats2half2_rn(w1.x, w1.y); st[7] = __floats2half2_rn(w1.z, w1.w);
    }

    for (int kt = 0; kt < KT; kt++) {
        const uint32_t sbuf = sbase + (uint32_t)(kt & 3) * STAGE_BYTES;

        // STS converted A chunk kt -> stage kt%4 (last read at kt-4: safe)
        *(uint4*)(dsm + (kt & 3) * STAGE_BYTES + soff1) = *(uint4*)(&st[0]);
        *(uint4*)(dsm + (kt & 3) * STAGE_BYTES + soff2) = *(uint4*)(&st[4]);

        // prefetch B chunk kt+2 -> stage (kt+2)%4 (!= (kt-1)%4: safe pre-barrier)
        if (kt + 2 < KT) {
            const int kb = (kt + 2) << 5;
            const uint32_t sp = sbase + (uint32_t)((kt + 2) & 3) * STAGE_BYTES;
            cp_async16(sp + 8192 + soff1, Bt + (size_t)lrow * K + kb + lc * 8);
            cp_async16(sp + 8192 + soff2, Bt + (size_t)(lrow + 64) * K + kb + lc * 8);
            cp_commit();
        }

        // LDG + convert A chunk kt+1 (overlaps compute)
        if (kt + 1 < KT) {
            const int kb = (kt + 1) << 5;
            const float* p1 = Af + (size_t)(m0 + lrow) * K + kb + lc * 8;
            const float* p2 = Af + (size_t)(m0 + lrow + 64) * K + kb + lc * 8;
            float4 v0 = *(const float4*)p1, v1 = *(const float4*)(p1 + 4);
            float4 w0 = *(const float4*)p2, w1 = *(const float4*)(p2 + 4);
            st[0] = __floats2half2_rn(v0.x, v0.y); st[1] = __floats2half2_rn(v0.z, v0.w);
            st[2] = __floats2half2_rn(v1.x, v1.y); st[3] = __floats2half2_rn(v1.z, v1.w);
            st[4] = __floats2half2_rn(w0.x, w0.y); st[5] = __floats2half2_rn(w0.z, w0.w);
            st[6] = __floats2half2_rn(w1.x, w1.y); st[7] = __floats2half2_rn(w1.z, w1.w);
        }

        if      (kt + 2 < KT) cp_wait<2>();
        else if (kt + 1 < KT) cp_wait<1>();
        else                  cp_wait<0>();
        __syncthreads();

        #pragma unroll
        for (int kk = 0; kk < 2; kk++) {
            uint32_t a[2][4], b[4][4];
            #pragma unroll
            for (int mi = 0; mi < 2; mi++) ldsm4(a[mi], sbuf + aoff[mi][kk]);
            #pragma unroll
            for (int nip = 0; nip < 4; nip++) ldsm4(b[nip], sbuf + 8192 + boff[nip][kk]);
            #pragma unroll
            for (int mi = 0; mi < 2; mi++)
                #pragma unroll
                for (int ni = 0; ni < 8; ni++)
                    mma16816(acc[mi][ni], a[mi], &b[ni >> 1][(ni & 1) * 2]);
        }
    }

    // epilogue: fp16 out
    const int gid = lane >> 2, tig = lane & 3;
    #pragma unroll
    for (int mi = 0; mi < 2; mi++) {
        const int r0 = m0 + wm * 32 + mi * 16 + gid;
        #pragma unroll
        for (int ni = 0; ni < 8; ni++) {
            const int col = tap * 128 + wn * 64 + ni * 8 + tig * 2;
            __half2 lo = __floats2half2_rn(acc[mi][ni][0], acc[mi][ni][1]);
            __half2 hi = __floats2half2_rn(acc[mi][ni][2], acc[mi][ni][3]);
            *(__half2*)&C[(size_t)r0 * NCOLS + col]       = lo;
            *(__half2*)&C[(size_t)(r0 + 8) * NCOLS + col] = hi;
        }
    }
}

// ---------------- gemm2: short-K (K=128, KT=4=NSTAGES, full prefetch) ----------------
__global__ void __launch_bounds__(256, 2)
gemm2_kernel(const __half* __restrict__ Ah,
             const __half* __restrict__ Bg,
             __half* __restrict__ C)
{
    extern __shared__ __align__(128) uint8_t dsm[];
    constexpr int K = NCLASS;   // 128

    const int tid  = threadIdx.x;
    const int lane = tid & 31;
    const int warp = tid >> 5;
    const int wm   = warp >> 1;
    const int wn   = warp & 1;
    const int tap  = blockIdx.x % TAPS;
    const int m0   = (blockIdx.x / TAPS) * 128;
    const __half* Bt = Bg + (size_t)tap * 128 * K;

    const int lrow = tid >> 2;
    const int lc   = tid & 3;
    const uint32_t soff1 = tile_off(lrow, lc);
    const uint32_t soff2 = soff1 + 64 * 64;

    const uint32_t sbase = smem_u32(dsm);
    uint32_t aoff[2][2], boff[4][2];
    {
        const int arow0 = wm * 32 + (lane & 7) + 8 * ((lane >> 3) & 1);
        const int acadd = lane >> 4;
        const int brow0 = wn * 64 + (lane & 7) + 8 * (lane >> 4);
        const int bcadd = (lane >> 3) & 1;
        #pragma unroll
        for (int kk = 0; kk < 2; kk++) {
            #pragma unroll
            for (int mi = 0; mi < 2; mi++)
                aoff[mi][kk] = tile_off(arow0 + mi * 16, kk * 2 + acadd);
            #pragma unroll
            for (int nip = 0; nip < 4; nip++)
                boff[nip][kk] = tile_off(brow0 + nip * 16, kk * 2 + bcadd);
        }
    }

    float acc[2][8][4];
    #pragma unroll
    for (int mi = 0; mi < 2; mi++)
        #pragma unroll
        for (int ni = 0; ni < 8; ni++)
            #pragma unroll
            for (int q = 0; q < 4; q++) acc[mi][ni][q] = 0.f;

    // full prefetch: all 4 K-chunks, one commit group each
    #pragma unroll
    for (int s = 0; s < 4; s++) {
        const uint32_t sp = sbase + s * STAGE_BYTES;
        const int kb = s << 5;
        cp_async16(sp + soff1, Ah + (size_t)(m0 + lrow) * K + kb + lc * 8);
        cp_async16(sp + soff2, Ah + (size_t)(m0 + lrow + 64) * K + kb + lc * 8);
        cp_async16(sp + 8192 + soff1, Bt + (size_t)lrow * K + kb + lc * 8);
        cp_async16(sp + 8192 + soff2, Bt + (size_t)(lrow + 64) * K + kb + lc * 8);
        cp_commit();
    }

    #pragma unroll
    for (int kt = 0; kt < 4; kt++) {
        if      (kt == 0) cp_wait<3>();
        else if (kt == 1) cp_wait<2>();
        else if (kt == 2) cp_wait<1>();
        else              cp_wait<0>();
        __syncthreads();

        const uint32_t sbuf = sbase + (uint32_t)kt * STAGE_BYTES;
        #pragma unroll
        for (int kk = 0; kk < 2; kk++) {
            uint32_t a[2][4], b[4][4];
            #pragma unroll
            for (int mi = 0; mi < 2; mi++) ldsm4(a[mi], sbuf + aoff[mi][kk]);
            #pragma unroll
            for (int nip = 0; nip < 4; nip++) ldsm4(b[nip], sbuf + 8192 + boff[nip][kk]);
            #pragma unroll
            for (int mi = 0; mi < 2; mi++)
                #pragma unroll
                for (int ni = 0; ni < 8; ni++)
                    mma16816(acc[mi][ni], a[mi], &b[ni >> 1][(ni & 1) * 2]);
        }
    }

    const int gid = lane >> 2, tig = lane & 3;
    #pragma unroll
    for (int mi = 0; mi < 2; mi++) {
        const int r0 = m0 + wm * 32 + mi * 16 + gid;
        #pragma unroll
        for (int ni = 0; ni < 8; ni++) {
            const int col = tap * 128 + wn * 64 + ni * 8 + tig * 2;
            __half2 lo = __floats2half2_rn(acc[mi][ni][0], acc[mi][ni][1]);
            __half2 hi = __floats2half2_rn(acc[mi][ni][2], acc[mi][ni][3]);
            *(__half2*)&C[(size_t)r0 * NCOLS + col]       = lo;
            *(__half2*)&C[(size_t)(r0 + 8) * NCOLS + col] = hi;
        }
    }
}

// ---------------- merged weight transpose + fp16 convert (W1: z<3, W2: z>=3) ----------------
__global__ void transpose_all_kernel(const float* __restrict__ W1, const float* __restrict__ W2,
                                     __half* __restrict__ W1h, __half* __restrict__ W2h)
{
    __shared__ float tile[32][33];
    const int z = blockIdx.z;
    const float* src; __half* dst; int E;
    if (z < 3) {
        E = EMSIZE;
        src = W1 + (size_t)z * EMSIZE * NCLASS;
        dst = W1h + (size_t)z * NCLASS * EMSIZE;
    } else {
        E = NCLASS;
        if (blockIdx.x >= NCLASS / 32) return;   // uniform per block
        src = W2 + (size_t)(z - 3) * NCLASS * NCLASS;
        dst = W2h + (size_t)(z - 3) * NCLASS * NCLASS;
    }
    const int e0 = blockIdx.x << 5, c0 = blockIdx.y << 5;
    #pragma unroll
    for (int j = 0; j < 32; j += 8)
        tile[threadIdx.y + j][threadIdx.x] =
            src[(size_t)(e0 + threadIdx.y + j) * NCLASS + c0 + threadIdx.x];
    __syncthreads();
    #pragma unroll
    for (int j = 0; j < 32; j += 8)
        dst[(size_t)(c0 + threadIdx.y + j) * E + e0 + threadIdx.x] =
            __float2half_rn(tile[threadIdx.x][threadIdx.y + j]);
}

// ---------------- combine + tanh (Y fp16 in) -> fp16 H ----------------
__global__ void combine_tanh_kernel(const __half* __restrict__ Yh,
                                    const float4* __restrict__ b1_4,
                                    uint2* __restrict__ H2)
{
    int idx = blockIdx.x * blockDim.x + threadIdx.x;   // < N_SENT*32
    int p = idx >> 5, q = idx & 31;
    const __half2* y0 = (const __half2*)&Yh[(size_t)p * NCOLS + 4 * q];
    float2 s0 = __half22float2(y0[0]), s1 = __half22float2(y0[1]);
    float cnt = 1.f;
    if (p >= 1) {
        const __half2* a = (const __half2*)&Yh[(size_t)(p - 1) * NCOLS + 128 + 4 * q];
        float2 a0 = __half22float2(a[0]), a1 = __half22float2(a[1]);
        s0.x += a0.x; s0.y += a0.y; s1.x += a1.x; s1.y += a1.y; cnt = 2.f;
    }
    if (p >= 2) {
        const __half2* a = (const __half2*)&Yh[(size_t)(p - 2) * NCOLS + 256 + 4 * q];
        float2 a0 = __half22float2(a[0]), a1 = __half22float2(a[1]);
        s0.x += a0.x; s0.y += a0.y; s1.x += a1.x; s1.y += a1.y; cnt = 3.f;
    }
    float4 b = b1_4[q];
    __half2 h01 = __floats2half2_rn(tanhf(s0.x + cnt * b.x), tanhf(s0.y + cnt * b.y));
    __half2 h23 = __floats2half2_rn(tanhf(s1.x + cnt * b.z), tanhf(s1.y + cnt * b.w));
    uint2 u;
    u.x = *reinterpret_cast<uint32_t*>(&h01);
    u.y = *reinterpret_cast<uint32_t*>(&h23);
    H2[(size_t)p * 32 + q] = u;
}

// ---------------- stage-2 combine + fallback + log_softmax (warp/row) ----------------
__global__ void stage2_softmax_kernel(const __half* __restrict__ G,
                                      const __half* __restrict__ Yh,
                                      const float4* __restrict__ W2_4,
                                      const float4* __restrict__ b1_4,
                                      const float4* __restrict__ b2_4,
                                      float4* __restrict__ out4)
{
    const int warp = threadIdx.x >> 5, lane = threadIdx.x & 31;
    const int i = blockIdx.x * 8 + warp;
    float4 z;
    float4 bb = b2_4[lane];
    if (i >= 2) {
        const __half2* g0 = (const __half2*)&G[(size_t)(i - 2) * NCOLS + 4 * lane];
        const __half2* g1 = (const __half2*)&G[(size_t)(i - 1) * NCOLS + 128 + 4 * lane];
        const __half2* g2 = (const __half2*)&G[(size_t)i * NCOLS + 256 + 4 * lane];
        float2 a0 = __half22float2(g0[0]), a1 = __half22float2(g0[1]);
        float2 b0 = __half22float2(g1[0]), b1v = __half22float2(g1[1]);
        float2 c0 = __half22float2(g2[0]), c1 = __half22float2(g2[1]);
        z.x = a0.x + b0.x + c0.x + 3.f * bb.x;
        z.y = a0.y + b0.y + c0.y + 3.f * bb.y;
        z.z = a1.x + b1v.x + c1.x + 3.f * bb.z;
        z.w = a1.y + b1v.y + c1.y + 3.f * bb.w;
    } else {
        // fallback: Z0 = tanh(Y[i, tap0] + b1) @ W2[0] + b2
        const __half2* y = (const __half2*)&Yh[(size_t)i * NCOLS + 4 * lane];
        float2 y0 = __half22float2(y[0]), y1 = __half22float2(y[1]);
        float4 b1f = b1_4[lane];
        float4 h;
        h.x = tanhf(y0.x + b1f.x); h.y = tanhf(y0.y + b1f.y);
        h.z = tanhf(y1.x + b1f.z); h.w = tanhf(y1.y + b1f.w);
        float4 acc = bb;
        for (int j = 0; j < 32; j++) {
            float hx = __shfl_sync(0xffffffffu, h.x, j);
            float hy = __shfl_sync(0xffffffffu, h.y, j);
            float hz = __shfl_sync(0xffffffffu, h.z, j);
            float hw = __shfl_sync(0xffffffffu, h.w, j);
            int k = 4 * j;
            float4 w0 = W2_4[(size_t)(k + 0) * 32 + lane];
            float4 w1 = W2_4[(size_t)(k + 1) * 32 + lane];
            float4 w2 = W2_4[(size_t)(k + 2) * 32 + lane];
            float4 w3 = W2_4[(size_t)(k + 3) * 32 + lane];
            acc.x += hx * w0.x + hy * w1.x + hz * w2.x + hw * w3.x;
            acc.y += hx * w0.y + hy * w1.y + hz * w2.y + hw * w3.y;
            acc.z += hx * w0.z + hy * w1.z + hz * w2.z + hw * w3.z;
            acc.w += hx * w0.w + hy * w1.w + hz * w2.w + hw * w3.w;
        }
        z = acc;
    }
    float m = fmaxf(fmaxf(z.x, z.y), fmaxf(z.z, z.w));
    #pragma unroll
    for (int o = 16; o > 0; o >>= 1) m = fmaxf(m, __shfl_xor_sync(0xffffffffu, m, o));
    float s = __expf(z.x - m) + __expf(z.y - m) + __expf(z.z - m) + __expf(z.w - m);
    #pragma unroll
    for (int o = 16; o > 0; o >>= 1) s += __shfl_xor_sync(0xffffffffu, s, o);
    float ls = m + __logf(s);
    out4[(size_t)i * 32 + lane] = make_float4(z.x - ls, z.y - ls, z.z - ls, z.w - ls);
}

// ---------------- launch ----------------
extern "C" void kernel_launch(void* const* d_in, const int* in_sizes, int n_in,
                              void* d_out, int out_size)
{
    const float* x  = (const float*)d_in[0];
    const float* W1 = (const float*)d_in[1];
    const float* b1 = (const float*)d_in[2];
    const float* W2 = (const float*)d_in[3];
    const float* b2 = (const float*)d_in[4];
    float* out = (float*)d_out;

    __half *Yh, *Gh, *Hh, *W1h, *W2h;
    cudaGetSymbolAddress((void**)&Yh,  g_Yh);
    cudaGetSymbolAddress((void**)&Gh,  g_Gh);
    cudaGetSymbolAddress((void**)&Hh,  g_Hh);
    cudaGetSymbolAddress((void**)&W1h, g_W1h);
    cudaGetSymbolAddress((void**)&W2h, g_W2h);

    static bool attr_done = false;
    if (!attr_done) {
        cudaFuncSetAttribute((const void*)gemm1_kernel,
                             cudaFuncAttributeMaxDynamicSharedMemorySize, SMEM_BYTES);
        cudaFuncSetAttribute((const void*)gemm2_kernel,
                             cudaFuncAttributeMaxDynamicSharedMemorySize, SMEM_BYTES);
        attr_done = true;
    }

    // 0: both weight transposes in one launch (keeps gemm2 at profiled slot 3)
    transpose_all_kernel<<<dim3(EMSIZE / 32, NCLASS / 32, 6), dim3(32, 8)>>>(W1, W2, W1h, W2h);

    // 1: K1  Y = x @ W1 per tap (fp16 out), grid 768, taps L2-share A
    gemm1_kernel<<<(N_SENT / 128) * TAPS, 256, SMEM_BYTES>>>(x, W1h, Yh, EMSIZE);

    // 2: H = tanh(shifted sum + cnt*b1) -> fp16
    combine_tanh_kernel<<<(N_SENT * 32) / 256, 256>>>(
        Yh, (const float4*)b1, (uint2*)Hh);

    // 3: G = H @ W2 (fp16 out)  <- ncu-profiled slot
    gemm2_kernel<<<(N_SENT / 128) * TAPS, 256, SMEM_BYTES>>>(Hh, W2h, Gh);

    // 4: Z combine + fallback + log_softmax
    stage2_softmax_kernel<<<N_SENT / 8, 256>>>(
        Gh, Yh, (const float4*)W2,
        (const float4*)b1, (const float4*)b2, (float4*)out);
}